// round 16
// baseline (speedup 1.0000x reference)
#include <cuda_runtime.h>
#include <cuda_bf16.h>
#include <cuda_fp16.h>
#include <math.h>
#include <stdint.h>

// Problem shape (fixed)
#define Bb 2
#define Hh 16
#define NN 2048
#define CC 1024
#define DD 64
#define MM_ (Bb * NN)        // 4096 rows

// Scratch (device globals — no allocation allowed)
__device__ __align__(16) __half g_qh[(size_t)Bb * Hh * NN * DD];  // fp16, scale-folded
__device__ __align__(16) __half g_kh[(size_t)Bb * Hh * NN * DD];
__device__ __align__(16) __half g_vh[(size_t)Bb * Hh * NN * DD];

__device__ __align__(16) __half g_xa[(size_t)MM_ * CC];            // fp16(x)
__device__ __align__(16) __half g_wq[(size_t)3 * CC * CC];         // [3072][1024] T
__device__ __align__(16) __half g_wp[(size_t)CC * CC];             // [1024][1024] T
__device__ __align__(16) __half g_att[(size_t)MM_ * CC];           // fp16(attention out)
__device__ __align__(16) float2 g_rope[(size_t)NN * 32];           // (cos,sin)[n][d]

// ---------------------------------------------------------------------------
// helpers
// ---------------------------------------------------------------------------
__device__ __forceinline__ void mma_f16(float* d,
                                        uint32_t a0, uint32_t a1, uint32_t a2, uint32_t a3,
                                        uint32_t b0, uint32_t b1)
{
    asm volatile(
        "mma.sync.aligned.m16n8k16.row.col.f32.f16.f16.f32 "
        "{%0,%1,%2,%3}, {%4,%5,%6,%7}, {%8,%9}, {%0,%1,%2,%3};"
        : "+f"(d[0]), "+f"(d[1]), "+f"(d[2]), "+f"(d[3])
        : "r"(a0), "r"(a1), "r"(a2), "r"(a3), "r"(b0), "r"(b1));
}

#define LDM4(r, addr)                                                        \
    asm volatile("ldmatrix.sync.aligned.m8n8.x4.shared.b16 {%0,%1,%2,%3}, [%4];" \
                 : "=r"((r)[0]), "=r"((r)[1]), "=r"((r)[2]), "=r"((r)[3])    \
                 : "r"(addr))

#define LDM4T(r, addr)                                                       \
    asm volatile("ldmatrix.sync.aligned.m8n8.x4.trans.shared.b16 {%0,%1,%2,%3}, [%4];" \
                 : "=r"((r)[0]), "=r"((r)[1]), "=r"((r)[2]), "=r"((r)[3])    \
                 : "r"(addr))

#define CP16(saddr, gptr)                                                    \
    asm volatile("cp.async.cg.shared.global [%0], [%1], 16;" :: "r"(saddr), "l"(gptr))

__device__ __forceinline__ uint32_t packh2(float lo, float hi) {
    __half2 h = __floats2half2_rn(lo, hi);
    return *(uint32_t*)&h;
}

__device__ __forceinline__ uint32_t ex2h2(uint32_t x) {
    uint32_t r;
    asm("ex2.approx.f16x2 %0, %1;" : "=r"(r) : "r"(x));
    return r;
}

// ---------------------------------------------------------------------------
// merged prep kernel: x->fp16 | rope table | W_qkv^T | W_proj^T
// ---------------------------------------------------------------------------
__global__ __launch_bounds__(256) void prep_all(
    const float* __restrict__ x, __half* __restrict__ xa,
    const float* __restrict__ wqkv, __half* __restrict__ wq,
    const float* __restrict__ wproj, __half* __restrict__ wp,
    float2* __restrict__ rope)
{
    __shared__ float t[32][33];
    int blk = blockIdx.x;

    if (blk < 4096) {                       // x -> fp16
        int i = blk * 256 + threadIdx.x;
        float4 v = ((const float4*)x)[i];
        ((__half2*)xa)[2 * i]     = __floats2half2_rn(v.x, v.y);
        ((__half2*)xa)[2 * i + 1] = __floats2half2_rn(v.z, v.w);
        return;
    }
    blk -= 4096;
    if (blk < 256) {                        // rope table
        int idx = blk * 256 + threadIdx.x;
        int n = idx >> 5, d = idx & 31;
        float inv_freq = powf(10000.f, -(float)d / 32.f);
        float a = (float)n * inv_freq;
        rope[idx] = make_float2(cosf(a), sinf(a));
        return;
    }
    blk -= 256;

    const float* W;
    __half* WT;
    int K, N, bx;
    if (blk < 3072) {                       // W_qkv
        W = wqkv; WT = wq; K = CC; N = 3 * CC;
        bx = blk % 96;  blk /= 96;
    } else {                                // W_proj
        blk -= 3072;
        W = wproj; WT = wp; K = CC; N = CC;
        bx = blk % 32;  blk /= 32;
    }
    int n0 = bx * 32, k0 = blk * 32;
    int c = threadIdx.x & 31, r0 = threadIdx.x >> 5;
    #pragma unroll
    for (int j = 0; j < 4; j++) {
        int r = r0 + j * 8;
        t[r][c] = W[(size_t)(k0 + r) * N + n0 + c];
    }
    __syncthreads();
    #pragma unroll
    for (int j = 0; j < 4; j++) {
        int r = r0 + j * 8;
        WT[(size_t)(n0 + r) * K + k0 + c] = __float2half_rn(t[c][r]);
    }
}

// ---------------------------------------------------------------------------
// GEMM mainloop (fp16, 3-stage, CTA 128x128, warp tile 32x64, k-tile 64).
// All 6 ldmatrix per s-step issued back-to-back before the 16 mma.
// ---------------------------------------------------------------------------
#define GSTG   32768
#define OFF_B  16384

#define GEMM_MAINLOOP(Aptr, Bptr)                                              \
    extern __shared__ __align__(16) char smg[];                                \
    const uint32_t sbase = (uint32_t)__cvta_generic_to_shared(smg);            \
    const int tid  = threadIdx.x;                                              \
    const int warp = tid >> 5, lane = tid & 31;                                \
    const int gID  = lane >> 2, tig = lane & 3;                                \
    const int bm = blockIdx.y * 128;                                           \
    const int bn = blockIdx.x * 128;                                           \
    const int m0 = (warp >> 1) * 32;                                           \
    const int n0 = (warp & 1) * 64;                                            \
    const __half* gsrc[8];                                                     \
    uint32_t      gdst[8];                                                     \
    _Pragma("unroll")                                                          \
    for (int j = 0; j < 8; j++) {                                              \
        int id = tid + j * 256;                                                \
        int pl = id >> 10;                                                     \
        int idx = id & 1023;                                                   \
        int r = idx >> 3, g = idx & 7;                                         \
        const __half* base = pl == 0 ? (Aptr) + (size_t)(bm + r) * K           \
                                     : (Bptr) + (size_t)(bn + r) * K;          \
        gsrc[j] = base + g * 8;                                                \
        gdst[j] = (uint32_t)(pl * OFF_B + r * 128 + ((g ^ (r & 7)) << 4));     \
    }                                                                          \
    uint32_t aoff[2]; int aswz[2];                                             \
    _Pragma("unroll")                                                          \
    for (int mi = 0; mi < 2; mi++) {                                           \
        int r = m0 + mi * 16 + (lane & 15);                                    \
        aoff[mi] = (uint32_t)(r * 128);                                        \
        aswz[mi] = r & 7;                                                      \
    }                                                                          \
    const int ghA = lane >> 4;                                                 \
    uint32_t boff[4]; int bswz[4];                                             \
    const int permB = ((lane >> 4) << 3) + (lane & 7);                         \
    const int gbB = (lane >> 3) & 1;                                           \
    _Pragma("unroll")                                                          \
    for (int ntp = 0; ntp < 4; ntp++) {                                        \
        int r = n0 + ntp * 16 + permB;                                         \
        boff[ntp] = (uint32_t)(OFF_B + r * 128);                               \
        bswz[ntp] = r & 7;                                                     \
    }                                                                          \
    float acc[2][8][4];                                                        \
    _Pragma("unroll")                                                          \
    for (int mi = 0; mi < 2; mi++)                                             \
        _Pragma("unroll")                                                      \
        for (int nt = 0; nt < 8; nt++)                                         \
            _Pragma("unroll")                                                  \
            for (int c = 0; c < 4; c++) acc[mi][nt][c] = 0.f;                  \
    const int NIT = K >> 6;                                                    \
    { for (int j_ = 0; j_ < 8; j_++) CP16(sbase + gdst[j_], gsrc[j_]); }       \
    asm volatile("cp.async.commit_group;");                                    \
    { for (int j_ = 0; j_ < 8; j_++)                                           \
          CP16(sbase + GSTG + gdst[j_], gsrc[j_] + 64); }                      \
    asm volatile("cp.async.commit_group;");                                    \
    int cur = 0;                                                               \
    _Pragma("unroll 1")                                                        \
    for (int it = 0; it < NIT; it++) {                                         \
        asm volatile("cp.async.wait_group 1;");                                \
        __syncthreads();                                                       \
        int nxt = cur + 2; if (nxt >= 3) nxt -= 3;                             \
        if (it + 2 < NIT) {                                                    \
            for (int j_ = 0; j_ < 8; j_++)                                     \
                CP16(sbase + (uint32_t)nxt * GSTG + gdst[j_],                  \
                     gsrc[j_] + (it + 2) * 64);                                \
        }                                                                      \
        asm volatile("cp.async.commit_group;");                                \
        const uint32_t stb = sbase + (uint32_t)cur * GSTG;                     \
        _Pragma("unroll")                                                      \
        for (int s = 0; s < 4; s++) {                                          \
            uint32_t af[2][4];                                                 \
            uint32_t b4[4][4];                                                 \
            _Pragma("unroll")                                                  \
            for (int mi = 0; mi < 2; mi++) {                                   \
                uint32_t ra = stb + aoff[mi]                                   \
                              + (uint32_t)((((s << 1) + ghA) ^ aswz[mi]) << 4);\
                LDM4(af[mi], ra);                                              \
            }                                                                  \
            _Pragma("unroll")                                                  \
            for (int ntp = 0; ntp < 4; ntp++) {                                \
                uint32_t rb = stb + boff[ntp]                                  \
                              + (uint32_t)((((s << 1) + gbB) ^ bswz[ntp]) << 4);\
                LDM4(b4[ntp], rb);                                             \
            }                                                                  \
            _Pragma("unroll")                                                  \
            for (int ntp = 0; ntp < 4; ntp++) {                                \
                _Pragma("unroll")                                              \
                for (int mi = 0; mi < 2; mi++) {                               \
                    mma_f16(acc[mi][2 * ntp],                                  \
                            af[mi][0], af[mi][1], af[mi][2], af[mi][3],        \
                            b4[ntp][0], b4[ntp][1]);                           \
                    mma_f16(acc[mi][2 * ntp + 1],                              \
                            af[mi][0], af[mi][1], af[mi][2], af[mi][3],        \
                            b4[ntp][2], b4[ntp][3]);                           \
                }                                                              \
            }                                                                  \
        }                                                                      \
        cur = cur + 1; if (cur == 3) cur = 0;                                  \
    }

// ---------------------------------------------------------------------------
// QKV GEMM with fused RoPE + head-split epilogue -> fp16 Q/K/V [B,H,N,d]
// ---------------------------------------------------------------------------
__global__ void __launch_bounds__(256, 2) gemm_qkv(
    const __half* __restrict__ A, const __half* __restrict__ B,
    const float2* __restrict__ rope,
    __half* __restrict__ Qo, __half* __restrict__ Ko, __half* __restrict__ Vo,
    int M, int N, int K)
{
    GEMM_MAINLOOP(A, B)

    const int t  = bn >> 10;
    const int h  = ((bn & 1023) + n0) >> 6;
    __half* outb = (t == 0) ? Qo : (t == 1) ? Ko : Vo;
    const float sc = (t == 0) ? 0.125f : 1.f;

    #pragma unroll
    for (int mi = 0; mi < 2; mi++) {
        int row0 = bm + m0 + mi * 16 + gID;
        #pragma unroll
        for (int rr = 0; rr < 2; rr++) {
            int r = row0 + rr * 8;
            int n = r & (NN - 1), bi = r >> 11;
            __half* dst = outb + ((size_t)(bi * Hh + h) * NN + n) * DD;
            if (t == 2) {
                #pragma unroll
                for (int nt = 0; nt < 8; nt++) {
                    int d0 = nt * 8 + 2 * tig;
                    *(__half2*)&dst[d0] =
                        __floats2half2_rn(acc[mi][nt][2 * rr], acc[mi][nt][2 * rr + 1]);
                }
            } else {
                #pragma unroll
                for (int nt = 0; nt < 4; nt++) {
                    int d0 = nt * 8 + 2 * tig;
                    float2 cs0 = rope[n * 32 + d0];
                    float2 cs1 = rope[n * 32 + d0 + 1];
                    float x10 = acc[mi][nt][2 * rr],     x11 = acc[mi][nt][2 * rr + 1];
                    float x20 = acc[mi][nt + 4][2 * rr], x21 = acc[mi][nt + 4][2 * rr + 1];
                    float lo0 = (x10 * cs0.x - x20 * cs0.y) * sc;
                    float lo1 = (x11 * cs1.x - x21 * cs1.y) * sc;
                    float hi0 = (x10 * cs0.y + x20 * cs0.x) * sc;
                    float hi1 = (x11 * cs1.y + x21 * cs1.x) * sc;
                    *(__half2*)&dst[d0]      = __floats2half2_rn(lo0, lo1);
                    *(__half2*)&dst[d0 + 32] = __floats2half2_rn(hi0, hi1);
                }
            }
        }
    }
}

// ---------------------------------------------------------------------------
// Projection GEMM: f32 out + bias
// ---------------------------------------------------------------------------
__global__ void __launch_bounds__(256, 2) gemm_f16(
    const __half* __restrict__ A, const __half* __restrict__ B,
    float* __restrict__ C, const float* __restrict__ bias,
    int M, int N, int K)
{
    GEMM_MAINLOOP(A, B)

    #pragma unroll
    for (int mi = 0; mi < 2; mi++) {
        int row = bm + m0 + mi * 16 + gID;
        #pragma unroll
        for (int nt = 0; nt < 8; nt++) {
            int col = bn + n0 + nt * 8 + 2 * tig;
            float b0 = bias[col];
            float b1 = bias[col + 1];
            float2 w0; w0.x = acc[mi][nt][0] + b0; w0.y = acc[mi][nt][1] + b1;
            float2 w1; w1.x = acc[mi][nt][2] + b0; w1.y = acc[mi][nt][3] + b1;
            *(float2*)&C[(size_t)row * N + col] = w0;
            *(float2*)&C[(size_t)(row + 8) * N + col] = w1;
        }
    }
}

// ---------------------------------------------------------------------------
// Flash attention, fp16 mma, warp M-tile 32; fp16x2 exp; batched frag loads.
// ---------------------------------------------------------------------------
#define FA_SMEM 32768
#define LOG2E 1.4426950408889634f

__global__ void __launch_bounds__(256, 1) flash_mma(
    const __half* __restrict__ Q, const __half* __restrict__ K,
    const __half* __restrict__ V, __half* __restrict__ O)
{
    extern __shared__ __align__(16) char sma[];
    const uint32_t sb = (uint32_t)__cvta_generic_to_shared(sma);

    const int bh = blockIdx.x;
    const int b = bh >> 4, h = bh & 15;
    const int tid = threadIdx.x;
    const int warp = tid >> 5, lane = tid & 31;
    const int gID = lane >> 2, tig = lane & 3;
    const int qbase = blockIdx.y * 256;

    {
        const __half* qg = Q + ((size_t)bh * NN + qbase) * DD;
        #pragma unroll
        for (int j = 0; j < 8; j++) {
            int id = tid + j * 256;
            int r = id >> 3, g = id & 7;
            CP16(sb + (uint32_t)(r * 128 + ((g ^ (r & 7)) << 4)), qg + r * DD + g * 8);
        }
        asm volatile("cp.async.commit_group;");
        asm volatile("cp.async.wait_group 0;");
        __syncthreads();
    }

    uint32_t aQ[2][4][4];
    #pragma unroll
    for (int mi = 0; mi < 2; mi++) {
        int qr = warp * 32 + mi * 16 + (lane & 15);
        #pragma unroll
        for (int s = 0; s < 4; s++) {
            int gran = 2 * s + (lane >> 4);
            LDM4(aQ[mi][s], sb + (uint32_t)(qr * 128 + ((gran ^ (qr & 7)) << 4)));
        }
    }
    __syncthreads();

    const __half* kbase = K + (size_t)bh * NN * DD;
    const __half* vbase = V + (size_t)bh * NN * DD;
#define KVLOAD(st, row0)                                                       \
    do { _Pragma("unroll")                                                     \
         for (int j_ = 0; j_ < 2; j_++) {                                      \
             int id_ = tid + j_ * 256;                                         \
             int r_ = id_ >> 3, g_ = id_ & 7;                                  \
             uint32_t sw_ = (uint32_t)(r_ * 128 + (((g_ ^ (r_ & 7))) << 4));   \
             CP16(sb + (uint32_t)(st) * 8192 + sw_,                            \
                  kbase + (size_t)(row0 + r_) * DD + g_ * 8);                  \
             CP16(sb + 16384u + (uint32_t)(st) * 8192 + sw_,                   \
                  vbase + (size_t)(row0 + r_) * DD + g_ * 8);                  \
         } } while (0)

    const int kr0  = lane & 7;
    const int gsel = (lane >> 3) & 1;
    const int sel  = lane >> 4;

    float of[2][8][4];
    #pragma unroll
    for (int mi = 0; mi < 2; mi++)
        #pragma unroll
        for (int i = 0; i < 8; i++)
            #pragma unroll
            for (int c = 0; c < 4; c++) of[mi][i][c] = 0.f;
    float mm[2][2], ll[2][2];
    #pragma unroll
    for (int mi = 0; mi < 2; mi++) {
        mm[mi][0] = -1e30f; mm[mi][1] = -1e30f;
        ll[mi][0] = 0.f;    ll[mi][1] = 0.f;
    }

    KVLOAD(0, 0);
    asm volatile("cp.async.commit_group;");

    #pragma unroll 1
    for (int t = 0; t < 32; t++) {
        asm volatile("cp.async.wait_group 0;");
        __syncthreads();
        if (t + 1 < 32) KVLOAD((t + 1) & 1, (t + 1) * 64);
        asm volatile("cp.async.commit_group;");

        const uint32_t Kst = sb + (uint32_t)((t & 1) * 8192);
        const uint32_t Vst = sb + 16384u + (uint32_t)((t & 1) * 8192);

        // ---- S = Q . K^T (batched K-frag loads per s-step) ----
        float sf[2][8][4];
        #pragma unroll
        for (int mi = 0; mi < 2; mi++)
            #pragma unroll
            for (int nt = 0; nt < 8; nt++)
                #pragma unroll
                for (int c = 0; c < 4; c++) sf[mi][nt][c] = 0.f;

        #pragma unroll
        for (int s = 0; s < 4; s++) {
            int physg = (2 * s + gsel) ^ kr0;
            uint32_t bb[4][4];
            #pragma unroll
            for (int ip = 0; ip < 4; ip++) {
                int row = (2 * ip + sel) * 8 + kr0;
                LDM4(bb[ip], Kst + (uint32_t)(row * 128 + (physg << 4)));
            }
            #pragma unroll
            for (int ip = 0; ip < 4; ip++) {
                #pragma unroll
                for (int mi = 0; mi < 2; mi++) {
                    mma_f16(sf[mi][2 * ip],
                            aQ[mi][s][0], aQ[mi][s][1], aQ[mi][s][2], aQ[mi][s][3],
                            bb[ip][0], bb[ip][1]);
                    mma_f16(sf[mi][2 * ip + 1],
                            aQ[mi][s][0], aQ[mi][s][1], aQ[mi][s][2], aQ[mi][s][3],
                            bb[ip][2], bb[ip][3]);
                }
            }
        }

        uint32_t ph[2][8][2];
        #pragma unroll
        for (int mi = 0; mi < 2; mi++) {
            float tmax0 = -1e30f, tmax1 = -1e30f;
            #pragma unroll
            for (int nt = 0; nt < 8; nt++) {
                tmax0 = fmaxf(tmax0, fmaxf(sf[mi][nt][0], sf[mi][nt][1]));
                tmax1 = fmaxf(tmax1, fmaxf(sf[mi][nt][2], sf[mi][nt][3]));
            }
            tmax0 = fmaxf(tmax0, __shfl_xor_sync(0xffffffffu, tmax0, 1));
            tmax0 = fmaxf(tmax0, __shfl_xor_sync(0xffffffffu, tmax0, 2));
            tmax1 = fmaxf(tmax1, __shfl_xor_sync(0xffffffffu, tmax1, 1));
            tmax1 = fmaxf(tmax1, __shfl_xor_sync(0xffffffffu, tmax1, 2));

            float mn0 = fmaxf(mm[mi][0], tmax0);
            float mn1 = fmaxf(mm[mi][1], tmax1);
            float al0 = __expf(mm[mi][0] - mn0);
            float al1 = __expf(mm[mi][1] - mn1);
            mm[mi][0] = mn0; mm[mi][1] = mn1;
            ll[mi][0] *= al0; ll[mi][1] *= al1;
            #pragma unroll
            for (int i = 0; i < 8; i++) {
                of[mi][i][0] *= al0; of[mi][i][1] *= al0;
                of[mi][i][2] *= al1; of[mi][i][3] *= al1;
            }
            float s0 = 0.f, s1 = 0.f;
            #pragma unroll
            for (int nt = 0; nt < 8; nt++) {
                uint32_t xa_ = packh2((sf[mi][nt][0] - mn0) * LOG2E,
                                      (sf[mi][nt][1] - mn0) * LOG2E);
                uint32_t xb_ = packh2((sf[mi][nt][2] - mn1) * LOG2E,
                                      (sf[mi][nt][3] - mn1) * LOG2E);
                uint32_t pa = ex2h2(xa_);
                uint32_t pb = ex2h2(xb_);
                ph[mi][nt][0] = pa;
                ph[mi][nt][1] = pb;
                float2 fa = __half22float2(*(__half2*)&pa);
                float2 fb = __half22float2(*(__half2*)&pb);
                s0 += fa.x + fa.y;
                s1 += fb.x + fb.y;
            }
            ll[mi][0] += s0;
            ll[mi][1] += s1;
        }

        // ---- O += P . V (batched V-frag loads per kk-step) ----
        #pragma unroll
        for (int kk = 0; kk < 4; kk++) {
            int row = 16 * kk + kr0 + 8 * gsel;
            uint32_t bb[4][4];
            #pragma unroll
            for (int jp = 0; jp < 4; jp++) {
                int physg = (2 * jp + sel) ^ kr0;
                LDM4T(bb[jp], Vst + (uint32_t)(row * 128 + (physg << 4)));
            }
            #pragma unroll
            for (int jp = 0; jp < 4; jp++) {
                #pragma unroll
                for (int mi = 0; mi < 2; mi++) {
                    mma_f16(of[mi][2 * jp],
                            ph[mi][2 * kk][0], ph[mi][2 * kk][1],
                            ph[mi][2 * kk + 1][0], ph[mi][2 * kk + 1][1],
                            bb[jp][0], bb[jp][1]);
                    mma_f16(of[mi][2 * jp + 1],
                            ph[mi][2 * kk][0], ph[mi][2 * kk][1],
                            ph[mi][2 * kk + 1][0], ph[mi][2 * kk + 1][1],
                            bb[jp][2], bb[jp][3]);
                }
            }
        }
    }

    #pragma unroll
    for (int mi = 0; mi < 2; mi++) {
        float l0 = ll[mi][0], l1 = ll[mi][1];
        l0 += __shfl_xor_sync(0xffffffffu, l0, 1);
        l0 += __shfl_xor_sync(0xffffffffu, l0, 2);
        l1 += __shfl_xor_sync(0xffffffffu, l1, 1);
        l1 += __shfl_xor_sync(0xffffffffu, l1, 2);
        float inv0 = 1.f / l0;
        float inv1 = 1.f / l1;

        int r0 = qbase + warp * 32 + mi * 16 + gID;
        int r1 = r0 + 8;
        size_t base0 = ((size_t)b * NN + r0) * CC + h * DD;
        size_t base1 = ((size_t)b * NN + r1) * CC + h * DD;
        #pragma unroll
        for (int i = 0; i < 8; i++) {
            int col = i * 8 + 2 * tig;
            *(__half2*)&O[base0 + col] =
                __floats2half2_rn(of[mi][i][0] * inv0, of[mi][i][1] * inv0);
            *(__half2*)&O[base1 + col] =
                __floats2half2_rn(of[mi][i][2] * inv1, of[mi][i][3] * inv1);
        }
    }
#undef KVLOAD
}

// ---------------------------------------------------------------------------
extern "C" void kernel_launch(void* const* d_in, const int* in_sizes, int n_in,
                              void* d_out, int out_size)
{
    const float* x      = (const float*)d_in[0];
    const float* w_qkv  = (const float*)d_in[1];
    const float* w_proj = (const float*)d_in[2];
    const float* b_proj = (const float*)d_in[3];
    float* out = (float*)d_out;

    __half *qh, *kh, *vh, *xa, *wq, *wp, *att;
    float2* rope;
    cudaGetSymbolAddress((void**)&qh,   g_qh);
    cudaGetSymbolAddress((void**)&kh,   g_kh);
    cudaGetSymbolAddress((void**)&vh,   g_vh);
    cudaGetSymbolAddress((void**)&xa,   g_xa);
    cudaGetSymbolAddress((void**)&wq,   g_wq);
    cudaGetSymbolAddress((void**)&wp,   g_wp);
    cudaGetSymbolAddress((void**)&att,  g_att);
    cudaGetSymbolAddress((void**)&rope, g_rope);

    static int attr_done = 0;
    if (!attr_done) {
        cudaFuncSetAttribute(gemm_qkv, cudaFuncAttributeMaxDynamicSharedMemorySize,
                             3 * GSTG);
        cudaFuncSetAttribute(gemm_f16, cudaFuncAttributeMaxDynamicSharedMemorySize,
                             3 * GSTG);
        cudaFuncSetAttribute(flash_mma, cudaFuncAttributeMaxDynamicSharedMemorySize,
                             FA_SMEM);
        attr_done = 1;
    }

    // 0) one merged prep kernel
    prep_all<<<8448, 256>>>(x, xa, w_qkv, wq, w_proj, wp, rope);

    // 1) QKV GEMM with fused RoPE + head split -> fp16 Q/K/V
    gemm_qkv<<<dim3(3 * CC / 128, MM_ / 128), 256, 3 * GSTG>>>(
        xa, wq, rope, qh, kh, vh, MM_, 3 * CC, CC);

    // 2) Attention (fp16 mma, m32 warp tiles, 256-row Q tiles, f16x2 exp)
    flash_mma<<<dim3(Bb * Hh, NN / 256), 256, FA_SMEM>>>(qh, kh, vh, att);

    // 3) Projection GEMM + bias (fp16 -> f32)
    gemm_f16<<<dim3(CC / 128, MM_ / 128), 256, 3 * GSTG>>>(
        att, wp, out, b_proj, MM_, CC, CC);
}

// round 17
// speedup vs baseline: 1.0195x; 1.0195x over previous
#include <cuda_runtime.h>
#include <cuda_bf16.h>
#include <cuda_fp16.h>
#include <math.h>
#include <stdint.h>

// Problem shape (fixed)
#define Bb 2
#define Hh 16
#define NN 2048
#define CC 1024
#define DD 64
#define MM_ (Bb * NN)        // 4096 rows

// Scratch (device globals — no allocation allowed)
__device__ __align__(16) __half g_qh[(size_t)Bb * Hh * NN * DD];  // fp16, scale-folded
__device__ __align__(16) __half g_kh[(size_t)Bb * Hh * NN * DD];
__device__ __align__(16) __half g_vh[(size_t)Bb * Hh * NN * DD];

__device__ __align__(16) __half g_xa[(size_t)MM_ * CC];            // fp16(x)
__device__ __align__(16) __half g_wq[(size_t)3 * CC * CC];         // [3072][1024] T
__device__ __align__(16) __half g_wp[(size_t)CC * CC];             // [1024][1024] T
__device__ __align__(16) __half g_att[(size_t)MM_ * CC];           // fp16(attention out)
__device__ __align__(16) float2 g_rope[(size_t)NN * 32];           // (cos,sin)[n][d]

// ---------------------------------------------------------------------------
// helpers
// ---------------------------------------------------------------------------
__device__ __forceinline__ void mma_f16(float* d,
                                        uint32_t a0, uint32_t a1, uint32_t a2, uint32_t a3,
                                        uint32_t b0, uint32_t b1)
{
    asm volatile(
        "mma.sync.aligned.m16n8k16.row.col.f32.f16.f16.f32 "
        "{%0,%1,%2,%3}, {%4,%5,%6,%7}, {%8,%9}, {%0,%1,%2,%3};"
        : "+f"(d[0]), "+f"(d[1]), "+f"(d[2]), "+f"(d[3])
        : "r"(a0), "r"(a1), "r"(a2), "r"(a3), "r"(b0), "r"(b1));
}

#define LDM4(r, addr)                                                        \
    asm volatile("ldmatrix.sync.aligned.m8n8.x4.shared.b16 {%0,%1,%2,%3}, [%4];" \
                 : "=r"((r)[0]), "=r"((r)[1]), "=r"((r)[2]), "=r"((r)[3])    \
                 : "r"(addr))

#define LDM4T(r, addr)                                                       \
    asm volatile("ldmatrix.sync.aligned.m8n8.x4.trans.shared.b16 {%0,%1,%2,%3}, [%4];" \
                 : "=r"((r)[0]), "=r"((r)[1]), "=r"((r)[2]), "=r"((r)[3])    \
                 : "r"(addr))

#define CP16(saddr, gptr)                                                    \
    asm volatile("cp.async.cg.shared.global [%0], [%1], 16;" :: "r"(saddr), "l"(gptr))

__device__ __forceinline__ uint32_t packh2(float lo, float hi) {
    __half2 h = __floats2half2_rn(lo, hi);
    return *(uint32_t*)&h;
}

__device__ __forceinline__ uint32_t ex2h2(uint32_t x) {
    uint32_t r;
    asm("ex2.approx.f16x2 %0, %1;" : "=r"(r) : "r"(x));
    return r;
}

// ---------------------------------------------------------------------------
// merged prep kernel: x->fp16 | rope table | W_qkv^T | W_proj^T
// ---------------------------------------------------------------------------
__global__ __launch_bounds__(256) void prep_all(
    const float* __restrict__ x, __half* __restrict__ xa,
    const float* __restrict__ wqkv, __half* __restrict__ wq,
    const float* __restrict__ wproj, __half* __restrict__ wp,
    float2* __restrict__ rope)
{
    __shared__ float t[32][33];
    int blk = blockIdx.x;

    if (blk < 4096) {                       // x -> fp16
        int i = blk * 256 + threadIdx.x;
        float4 v = ((const float4*)x)[i];
        ((__half2*)xa)[2 * i]     = __floats2half2_rn(v.x, v.y);
        ((__half2*)xa)[2 * i + 1] = __floats2half2_rn(v.z, v.w);
        return;
    }
    blk -= 4096;
    if (blk < 256) {                        // rope table
        int idx = blk * 256 + threadIdx.x;
        int n = idx >> 5, d = idx & 31;
        float inv_freq = powf(10000.f, -(float)d / 32.f);
        float a = (float)n * inv_freq;
        rope[idx] = make_float2(cosf(a), sinf(a));
        return;
    }
    blk -= 256;

    const float* W;
    __half* WT;
    int K, N, bx;
    if (blk < 3072) {                       // W_qkv
        W = wqkv; WT = wq; K = CC; N = 3 * CC;
        bx = blk % 96;  blk /= 96;
    } else {                                // W_proj
        blk -= 3072;
        W = wproj; WT = wp; K = CC; N = CC;
        bx = blk % 32;  blk /= 32;
    }
    int n0 = bx * 32, k0 = blk * 32;
    int c = threadIdx.x & 31, r0 = threadIdx.x >> 5;
    #pragma unroll
    for (int j = 0; j < 4; j++) {
        int r = r0 + j * 8;
        t[r][c] = W[(size_t)(k0 + r) * N + n0 + c];
    }
    __syncthreads();
    #pragma unroll
    for (int j = 0; j < 4; j++) {
        int r = r0 + j * 8;
        WT[(size_t)(n0 + r) * K + k0 + c] = __float2half_rn(t[c][r]);
    }
}

// ---------------------------------------------------------------------------
// GEMM mainloop: fp16, 3-stage, CTA 64x128, 128 threads (4 warps, 2x2),
// warp tile 32x64, k-tile 64. Stage = A 8KB @0 + B 16KB @8192 = 24KB, x3.
// 3 CTA/SM: small barrier scope + inter-CTA overlap.
// ---------------------------------------------------------------------------
#define GSTG   24576
#define OFF_B  8192

#define GEMM_MAINLOOP(Aptr, Bptr)                                              \
    extern __shared__ __align__(16) char smg[];                                \
    const uint32_t sbase = (uint32_t)__cvta_generic_to_shared(smg);            \
    const int tid  = threadIdx.x;                                              \
    const int warp = tid >> 5, lane = tid & 31;                                \
    const int gID  = lane >> 2, tig = lane & 3;                                \
    const int bm = blockIdx.y * 64;                                            \
    const int bn = blockIdx.x * 128;                                           \
    const int m0 = (warp >> 1) * 32;                                           \
    const int n0 = (warp & 1) * 64;                                            \
    const __half* gsrc[12];                                                    \
    uint32_t      gdst[12];                                                    \
    _Pragma("unroll")                                                          \
    for (int j = 0; j < 12; j++) {                                             \
        int id = tid + j * 128;            /* 0..1535 */                       \
        if (id < 512) {                                                        \
            int r = id >> 3, g = id & 7;                                       \
            gsrc[j] = (Aptr) + (size_t)(bm + r) * K + g * 8;                   \
            gdst[j] = (uint32_t)(r * 128 + ((g ^ (r & 7)) << 4));              \
        } else {                                                               \
            int idx = id - 512;                                                \
            int r = idx >> 3, g = idx & 7;                                     \
            gsrc[j] = (Bptr) + (size_t)(bn + r) * K + g * 8;                   \
            gdst[j] = (uint32_t)(OFF_B + r * 128 + ((g ^ (r & 7)) << 4));      \
        }                                                                      \
    }                                                                          \
    uint32_t aoff[2]; int aswz[2];                                             \
    _Pragma("unroll")                                                          \
    for (int mi = 0; mi < 2; mi++) {                                           \
        int r = m0 + mi * 16 + (lane & 15);                                    \
        aoff[mi] = (uint32_t)(r * 128);                                        \
        aswz[mi] = r & 7;                                                      \
    }                                                                          \
    const int ghA = lane >> 4;                                                 \
    uint32_t boff[4]; int bswz[4];                                             \
    const int permB = ((lane >> 4) << 3) + (lane & 7);                         \
    const int gbB = (lane >> 3) & 1;                                           \
    _Pragma("unroll")                                                          \
    for (int ntp = 0; ntp < 4; ntp++) {                                        \
        int r = n0 + ntp * 16 + permB;                                         \
        boff[ntp] = (uint32_t)(OFF_B + r * 128);                               \
        bswz[ntp] = r & 7;                                                     \
    }                                                                          \
    float acc[2][8][4];                                                        \
    _Pragma("unroll")                                                          \
    for (int mi = 0; mi < 2; mi++)                                             \
        _Pragma("unroll")                                                      \
        for (int nt = 0; nt < 8; nt++)                                         \
            _Pragma("unroll")                                                  \
            for (int c = 0; c < 4; c++) acc[mi][nt][c] = 0.f;                  \
    const int NIT = K >> 6;                                                    \
    { for (int j_ = 0; j_ < 12; j_++) CP16(sbase + gdst[j_], gsrc[j_]); }      \
    asm volatile("cp.async.commit_group;");                                    \
    { for (int j_ = 0; j_ < 12; j_++)                                          \
          CP16(sbase + GSTG + gdst[j_], gsrc[j_] + 64); }                      \
    asm volatile("cp.async.commit_group;");                                    \
    int cur = 0;                                                               \
    _Pragma("unroll 1")                                                        \
    for (int it = 0; it < NIT; it++) {                                         \
        asm volatile("cp.async.wait_group 1;");                                \
        __syncthreads();                                                       \
        int nxt = cur + 2; if (nxt >= 3) nxt -= 3;                             \
        if (it + 2 < NIT) {                                                    \
            for (int j_ = 0; j_ < 12; j_++)                                    \
                CP16(sbase + (uint32_t)nxt * GSTG + gdst[j_],                  \
                     gsrc[j_] + (it + 2) * 64);                                \
        }                                                                      \
        asm volatile("cp.async.commit_group;");                                \
        const uint32_t stb = sbase + (uint32_t)cur * GSTG;                     \
        _Pragma("unroll")                                                      \
        for (int s = 0; s < 4; s++) {                                          \
            uint32_t af[2][4];                                                 \
            uint32_t b4[4][4];                                                 \
            _Pragma("unroll")                                                  \
            for (int mi = 0; mi < 2; mi++) {                                   \
                uint32_t ra = stb + aoff[mi]                                   \
                              + (uint32_t)((((s << 1) + ghA) ^ aswz[mi]) << 4);\
                LDM4(af[mi], ra);                                              \
            }                                                                  \
            _Pragma("unroll")                                                  \
            for (int ntp = 0; ntp < 4; ntp++) {                                \
                uint32_t rb = stb + boff[ntp]                                  \
                              + (uint32_t)((((s << 1) + gbB) ^ bswz[ntp]) << 4);\
                LDM4(b4[ntp], rb);                                             \
            }                                                                  \
            _Pragma("unroll")                                                  \
            for (int ntp = 0; ntp < 4; ntp++) {                                \
                _Pragma("unroll")                                              \
                for (int mi = 0; mi < 2; mi++) {                               \
                    mma_f16(acc[mi][2 * ntp],                                  \
                            af[mi][0], af[mi][1], af[mi][2], af[mi][3],        \
                            b4[ntp][0], b4[ntp][1]);                           \
                    mma_f16(acc[mi][2 * ntp + 1],                              \
                            af[mi][0], af[mi][1], af[mi][2], af[mi][3],        \
                            b4[ntp][2], b4[ntp][3]);                           \
                }                                                              \
            }                                                                  \
        }                                                                      \
        cur = cur + 1; if (cur == 3) cur = 0;                                  \
    }

// ---------------------------------------------------------------------------
// QKV GEMM with fused RoPE + head-split epilogue -> fp16 Q/K/V [B,H,N,d]
// ---------------------------------------------------------------------------
__global__ void __launch_bounds__(128, 3) gemm_qkv(
    const __half* __restrict__ A, const __half* __restrict__ B,
    const float2* __restrict__ rope,
    __half* __restrict__ Qo, __half* __restrict__ Ko, __half* __restrict__ Vo,
    int M, int N, int K)
{
    GEMM_MAINLOOP(A, B)

    const int col0 = bn + n0;              // warp n-tile = one head
    const int t  = col0 >> 10;
    const int h  = (col0 & 1023) >> 6;
    __half* outb = (t == 0) ? Qo : (t == 1) ? Ko : Vo;
    const float sc = (t == 0) ? 0.125f : 1.f;

    #pragma unroll
    for (int mi = 0; mi < 2; mi++) {
        int row0 = bm + m0 + mi * 16 + gID;
        #pragma unroll
        for (int rr = 0; rr < 2; rr++) {
            int r = row0 + rr * 8;
            int n = r & (NN - 1), bi = r >> 11;
            __half* dst = outb + ((size_t)(bi * Hh + h) * NN + n) * DD;
            if (t == 2) {
                #pragma unroll
                for (int nt = 0; nt < 8; nt++) {
                    int d0 = nt * 8 + 2 * tig;
                    *(__half2*)&dst[d0] =
                        __floats2half2_rn(acc[mi][nt][2 * rr], acc[mi][nt][2 * rr + 1]);
                }
            } else {
                #pragma unroll
                for (int nt = 0; nt < 4; nt++) {
                    int d0 = nt * 8 + 2 * tig;
                    float2 cs0 = rope[n * 32 + d0];
                    float2 cs1 = rope[n * 32 + d0 + 1];
                    float x10 = acc[mi][nt][2 * rr],     x11 = acc[mi][nt][2 * rr + 1];
                    float x20 = acc[mi][nt + 4][2 * rr], x21 = acc[mi][nt + 4][2 * rr + 1];
                    float lo0 = (x10 * cs0.x - x20 * cs0.y) * sc;
                    float lo1 = (x11 * cs1.x - x21 * cs1.y) * sc;
                    float hi0 = (x10 * cs0.y + x20 * cs0.x) * sc;
                    float hi1 = (x11 * cs1.y + x21 * cs1.x) * sc;
                    *(__half2*)&dst[d0]      = __floats2half2_rn(lo0, lo1);
                    *(__half2*)&dst[d0 + 32] = __floats2half2_rn(hi0, hi1);
                }
            }
        }
    }
}

// ---------------------------------------------------------------------------
// Projection GEMM: f32 out + bias
// ---------------------------------------------------------------------------
__global__ void __launch_bounds__(128, 3) gemm_f16(
    const __half* __restrict__ A, const __half* __restrict__ B,
    float* __restrict__ C, const float* __restrict__ bias,
    int M, int N, int K)
{
    GEMM_MAINLOOP(A, B)

    #pragma unroll
    for (int mi = 0; mi < 2; mi++) {
        int row = bm + m0 + mi * 16 + gID;
        #pragma unroll
        for (int nt = 0; nt < 8; nt++) {
            int col = bn + n0 + nt * 8 + 2 * tig;
            float b0 = bias[col];
            float b1 = bias[col + 1];
            float2 w0; w0.x = acc[mi][nt][0] + b0; w0.y = acc[mi][nt][1] + b1;
            float2 w1; w1.x = acc[mi][nt][2] + b0; w1.y = acc[mi][nt][3] + b1;
            *(float2*)&C[(size_t)row * N + col] = w0;
            *(float2*)&C[(size_t)(row + 8) * N + col] = w1;
        }
    }
}

// ---------------------------------------------------------------------------
// Flash attention, fp16 mma, warp M-tile 32; fp16x2 exp; batched frag loads.
// ---------------------------------------------------------------------------
#define FA_SMEM 32768
#define LOG2E 1.4426950408889634f

__global__ void __launch_bounds__(256, 1) flash_mma(
    const __half* __restrict__ Q, const __half* __restrict__ K,
    const __half* __restrict__ V, __half* __restrict__ O)
{
    extern __shared__ __align__(16) char sma[];
    const uint32_t sb = (uint32_t)__cvta_generic_to_shared(sma);

    const int bh = blockIdx.x;
    const int b = bh >> 4, h = bh & 15;
    const int tid = threadIdx.x;
    const int warp = tid >> 5, lane = tid & 31;
    const int gID = lane >> 2, tig = lane & 3;
    const int qbase = blockIdx.y * 256;

    {
        const __half* qg = Q + ((size_t)bh * NN + qbase) * DD;
        #pragma unroll
        for (int j = 0; j < 8; j++) {
            int id = tid + j * 256;
            int r = id >> 3, g = id & 7;
            CP16(sb + (uint32_t)(r * 128 + ((g ^ (r & 7)) << 4)), qg + r * DD + g * 8);
        }
        asm volatile("cp.async.commit_group;");
        asm volatile("cp.async.wait_group 0;");
        __syncthreads();
    }

    uint32_t aQ[2][4][4];
    #pragma unroll
    for (int mi = 0; mi < 2; mi++) {
        int qr = warp * 32 + mi * 16 + (lane & 15);
        #pragma unroll
        for (int s = 0; s < 4; s++) {
            int gran = 2 * s + (lane >> 4);
            LDM4(aQ[mi][s], sb + (uint32_t)(qr * 128 + ((gran ^ (qr & 7)) << 4)));
        }
    }
    __syncthreads();

    const __half* kbase = K + (size_t)bh * NN * DD;
    const __half* vbase = V + (size_t)bh * NN * DD;
#define KVLOAD(st, row0)                                                       \
    do { _Pragma("unroll")                                                     \
         for (int j_ = 0; j_ < 2; j_++) {                                      \
             int id_ = tid + j_ * 256;                                         \
             int r_ = id_ >> 3, g_ = id_ & 7;                                  \
             uint32_t sw_ = (uint32_t)(r_ * 128 + (((g_ ^ (r_ & 7))) << 4));   \
             CP16(sb + (uint32_t)(st) * 8192 + sw_,                            \
                  kbase + (size_t)(row0 + r_) * DD + g_ * 8);                  \
             CP16(sb + 16384u + (uint32_t)(st) * 8192 + sw_,                   \
                  vbase + (size_t)(row0 + r_) * DD + g_ * 8);                  \
         } } while (0)

    const int kr0  = lane & 7;
    const int gsel = (lane >> 3) & 1;
    const int sel  = lane >> 4;

    float of[2][8][4];
    #pragma unroll
    for (int mi = 0; mi < 2; mi++)
        #pragma unroll
        for (int i = 0; i < 8; i++)
            #pragma unroll
            for (int c = 0; c < 4; c++) of[mi][i][c] = 0.f;
    float mm[2][2], ll[2][2];
    #pragma unroll
    for (int mi = 0; mi < 2; mi++) {
        mm[mi][0] = -1e30f; mm[mi][1] = -1e30f;
        ll[mi][0] = 0.f;    ll[mi][1] = 0.f;
    }

    KVLOAD(0, 0);
    asm volatile("cp.async.commit_group;");

    #pragma unroll 1
    for (int t = 0; t < 32; t++) {
        asm volatile("cp.async.wait_group 0;");
        __syncthreads();
        if (t + 1 < 32) KVLOAD((t + 1) & 1, (t + 1) * 64);
        asm volatile("cp.async.commit_group;");

        const uint32_t Kst = sb + (uint32_t)((t & 1) * 8192);
        const uint32_t Vst = sb + 16384u + (uint32_t)((t & 1) * 8192);

        float sf[2][8][4];
        #pragma unroll
        for (int mi = 0; mi < 2; mi++)
            #pragma unroll
            for (int nt = 0; nt < 8; nt++)
                #pragma unroll
                for (int c = 0; c < 4; c++) sf[mi][nt][c] = 0.f;

        #pragma unroll
        for (int s = 0; s < 4; s++) {
            int physg = (2 * s + gsel) ^ kr0;
            uint32_t bb[4][4];
            #pragma unroll
            for (int ip = 0; ip < 4; ip++) {
                int row = (2 * ip + sel) * 8 + kr0;
                LDM4(bb[ip], Kst + (uint32_t)(row * 128 + (physg << 4)));
            }
            #pragma unroll
            for (int ip = 0; ip < 4; ip++) {
                #pragma unroll
                for (int mi = 0; mi < 2; mi++) {
                    mma_f16(sf[mi][2 * ip],
                            aQ[mi][s][0], aQ[mi][s][1], aQ[mi][s][2], aQ[mi][s][3],
                            bb[ip][0], bb[ip][1]);
                    mma_f16(sf[mi][2 * ip + 1],
                            aQ[mi][s][0], aQ[mi][s][1], aQ[mi][s][2], aQ[mi][s][3],
                            bb[ip][2], bb[ip][3]);
                }
            }
        }

        uint32_t ph[2][8][2];
        #pragma unroll
        for (int mi = 0; mi < 2; mi++) {
            float tmax0 = -1e30f, tmax1 = -1e30f;
            #pragma unroll
            for (int nt = 0; nt < 8; nt++) {
                tmax0 = fmaxf(tmax0, fmaxf(sf[mi][nt][0], sf[mi][nt][1]));
                tmax1 = fmaxf(tmax1, fmaxf(sf[mi][nt][2], sf[mi][nt][3]));
            }
            tmax0 = fmaxf(tmax0, __shfl_xor_sync(0xffffffffu, tmax0, 1));
            tmax0 = fmaxf(tmax0, __shfl_xor_sync(0xffffffffu, tmax0, 2));
            tmax1 = fmaxf(tmax1, __shfl_xor_sync(0xffffffffu, tmax1, 1));
            tmax1 = fmaxf(tmax1, __shfl_xor_sync(0xffffffffu, tmax1, 2));

            float mn0 = fmaxf(mm[mi][0], tmax0);
            float mn1 = fmaxf(mm[mi][1], tmax1);
            float al0 = __expf(mm[mi][0] - mn0);
            float al1 = __expf(mm[mi][1] - mn1);
            mm[mi][0] = mn0; mm[mi][1] = mn1;
            ll[mi][0] *= al0; ll[mi][1] *= al1;
            #pragma unroll
            for (int i = 0; i < 8; i++) {
                of[mi][i][0] *= al0; of[mi][i][1] *= al0;
                of[mi][i][2] *= al1; of[mi][i][3] *= al1;
            }
            float s0 = 0.f, s1 = 0.f;
            #pragma unroll
            for (int nt = 0; nt < 8; nt++) {
                uint32_t xa_ = packh2((sf[mi][nt][0] - mn0) * LOG2E,
                                      (sf[mi][nt][1] - mn0) * LOG2E);
                uint32_t xb_ = packh2((sf[mi][nt][2] - mn1) * LOG2E,
                                      (sf[mi][nt][3] - mn1) * LOG2E);
                uint32_t pa = ex2h2(xa_);
                uint32_t pb = ex2h2(xb_);
                ph[mi][nt][0] = pa;
                ph[mi][nt][1] = pb;
                float2 fa = __half22float2(*(__half2*)&pa);
                float2 fb = __half22float2(*(__half2*)&pb);
                s0 += fa.x + fa.y;
                s1 += fb.x + fb.y;
            }
            ll[mi][0] += s0;
            ll[mi][1] += s1;
        }

        #pragma unroll
        for (int kk = 0; kk < 4; kk++) {
            int row = 16 * kk + kr0 + 8 * gsel;
            uint32_t bb[4][4];
            #pragma unroll
            for (int jp = 0; jp < 4; jp++) {
                int physg = (2 * jp + sel) ^ kr0;
                LDM4T(bb[jp], Vst + (uint32_t)(row * 128 + (physg << 4)));
            }
            #pragma unroll
            for (int jp = 0; jp < 4; jp++) {
                #pragma unroll
                for (int mi = 0; mi < 2; mi++) {
                    mma_f16(of[mi][2 * jp],
                            ph[mi][2 * kk][0], ph[mi][2 * kk][1],
                            ph[mi][2 * kk + 1][0], ph[mi][2 * kk + 1][1],
                            bb[jp][0], bb[jp][1]);
                    mma_f16(of[mi][2 * jp + 1],
                            ph[mi][2 * kk][0], ph[mi][2 * kk][1],
                            ph[mi][2 * kk + 1][0], ph[mi][2 * kk + 1][1],
                            bb[jp][2], bb[jp][3]);
                }
            }
        }
    }

    #pragma unroll
    for (int mi = 0; mi < 2; mi++) {
        float l0 = ll[mi][0], l1 = ll[mi][1];
        l0 += __shfl_xor_sync(0xffffffffu, l0, 1);
        l0 += __shfl_xor_sync(0xffffffffu, l0, 2);
        l1 += __shfl_xor_sync(0xffffffffu, l1, 1);
        l1 += __shfl_xor_sync(0xffffffffu, l1, 2);
        float inv0 = 1.f / l0;
        float inv1 = 1.f / l1;

        int r0 = qbase + warp * 32 + mi * 16 + gID;
        int r1 = r0 + 8;
        size_t base0 = ((size_t)b * NN + r0) * CC + h * DD;
        size_t base1 = ((size_t)b * NN + r1) * CC + h * DD;
        #pragma unroll
        for (int i = 0; i < 8; i++) {
            int col = i * 8 + 2 * tig;
            *(__half2*)&O[base0 + col] =
                __floats2half2_rn(of[mi][i][0] * inv0, of[mi][i][1] * inv0);
            *(__half2*)&O[base1 + col] =
                __floats2half2_rn(of[mi][i][2] * inv1, of[mi][i][3] * inv1);
        }
    }
#undef KVLOAD
}

// ---------------------------------------------------------------------------
extern "C" void kernel_launch(void* const* d_in, const int* in_sizes, int n_in,
                              void* d_out, int out_size)
{
    const float* x      = (const float*)d_in[0];
    const float* w_qkv  = (const float*)d_in[1];
    const float* w_proj = (const float*)d_in[2];
    const float* b_proj = (const float*)d_in[3];
    float* out = (float*)d_out;

    __half *qh, *kh, *vh, *xa, *wq, *wp, *att;
    float2* rope;
    cudaGetSymbolAddress((void**)&qh,   g_qh);
    cudaGetSymbolAddress((void**)&kh,   g_kh);
    cudaGetSymbolAddress((void**)&vh,   g_vh);
    cudaGetSymbolAddress((void**)&xa,   g_xa);
    cudaGetSymbolAddress((void**)&wq,   g_wq);
    cudaGetSymbolAddress((void**)&wp,   g_wp);
    cudaGetSymbolAddress((void**)&att,  g_att);
    cudaGetSymbolAddress((void**)&rope, g_rope);

    static int attr_done = 0;
    if (!attr_done) {
        cudaFuncSetAttribute(gemm_qkv, cudaFuncAttributeMaxDynamicSharedMemorySize,
                             3 * GSTG);
        cudaFuncSetAttribute(gemm_f16, cudaFuncAttributeMaxDynamicSharedMemorySize,
                             3 * GSTG);
        cudaFuncSetAttribute(flash_mma, cudaFuncAttributeMaxDynamicSharedMemorySize,
                             FA_SMEM);
        attr_done = 1;
    }

    // 0) one merged prep kernel
    prep_all<<<8448, 256>>>(x, xa, w_qkv, wq, w_proj, wp, rope);

    // 1) QKV GEMM with fused RoPE + head split -> fp16 Q/K/V
    gemm_qkv<<<dim3(3 * CC / 128, MM_ / 64), 128, 3 * GSTG>>>(
        xa, wq, rope, qh, kh, vh, MM_, 3 * CC, CC);

    // 2) Attention (fp16 mma, m32 warp tiles, 256-row Q tiles, f16x2 exp)
    flash_mma<<<dim3(Bb * Hh, NN / 256), 256, FA_SMEM>>>(qh, kh, vh, att);

    // 3) Projection GEMM + bias (fp16 -> f32)
    gemm_f16<<<dim3(CC / 128, MM_ / 64), 128, 3 * GSTG>>>(
        att, wp, out, b_proj, MM_, CC, CC);
}